// round 1
// baseline (speedup 1.0000x reference)
#include <cuda_runtime.h>
#include <math.h>

// Problem constants (fixed by the dataset)
#define N_NODES_MAX 50000
#define D 64          // D_IN = D_OUT = 64
#define N_REL 8

// Scratch (no cudaMalloc allowed)
__device__ float g_agg[(size_t)N_NODES_MAX * D];   // 12.8 MB
__device__ float g_cnt[N_NODES_MAX];
__device__ float g_w[N_REL * 2 * D];               // w = W_r.sum(-1) : [8,128]

// ---------------------------------------------------------------------------
// Kernel 1: w[r][j] = sum_k W_r[r][j][k]   (8 blocks x 128 threads)
// ---------------------------------------------------------------------------
__global__ void wsum_kernel(const float* __restrict__ W_r) {
    int r = blockIdx.x;
    int j = threadIdx.x;
    const float4* row = (const float4*)(W_r + ((size_t)r * 2 * D + j) * D);
    float4 s = make_float4(0.f, 0.f, 0.f, 0.f);
#pragma unroll
    for (int k = 0; k < D / 4; k++) {
        float4 v = __ldg(row + k);
        s.x += v.x; s.y += v.y; s.z += v.z; s.w += v.w;
    }
    g_w[r * 2 * D + j] = (s.x + s.y) + (s.z + s.w);
}

// ---------------------------------------------------------------------------
// Kernel 2: zero agg + cnt (graph replays, so scratch must be re-zeroed)
// ---------------------------------------------------------------------------
__global__ void zero_kernel(int n_nodes) {
    int idx = blockIdx.x * blockDim.x + threadIdx.x;
    int n_agg4 = n_nodes * (D / 4);
    if (idx < n_agg4) ((float4*)g_agg)[idx] = make_float4(0.f, 0.f, 0.f, 0.f);
    if (idx < n_nodes) g_cnt[idx] = 0.f;
}

// ---------------------------------------------------------------------------
// Kernel 3: edge phase. Half-warp (16 lanes) per edge; lane holds float4 (4 dims).
//   logit = <x[dst], w_dst[rel]> + <x[src], w_src[rel]>
//   gate  = sigmoid(logit)
//   red.global.add.v4.f32  agg[dst] += x[src]*gate ;  cnt[dst] += 1
// ---------------------------------------------------------------------------
__global__ void edge_kernel(const float* __restrict__ x,
                            const int* __restrict__ src,
                            const int* __restrict__ dst,
                            const int* __restrict__ rel,
                            int E) {
    __shared__ float4 wsm[N_REL * 32];   // w[8][128] as float4
    for (int i = threadIdx.x; i < N_REL * 32; i += blockDim.x)
        wsm[i] = ((const float4*)g_w)[i];
    __syncthreads();

    int warp = (blockIdx.x * blockDim.x + threadIdx.x) >> 5;
    int lane = threadIdx.x & 31;
    int half = lane >> 4;        // which edge within the warp
    int sub  = lane & 15;        // 16 lanes x float4 = 64 dims

    int e = warp * 2 + half;
    bool valid = (e < E);
    int ec = valid ? e : (E - 1);

    int s = __ldg(src + ec);
    int d = __ldg(dst + ec);
    int r = __ldg(rel + ec);

    const float4* x4 = (const float4*)x;
    float4 xs = __ldg(x4 + (size_t)s * (D / 4) + sub);
    float4 xd = __ldg(x4 + (size_t)d * (D / 4) + sub);
    float4 wd = wsm[r * 32 + sub];        // w_dst part (first 64)
    float4 ws = wsm[r * 32 + 16 + sub];   // w_src part (second 64)

    float p = xd.x * wd.x + xd.y * wd.y + xd.z * wd.z + xd.w * wd.w
            + xs.x * ws.x + xs.y * ws.y + xs.z * ws.z + xs.w * ws.w;
    // reduce within the 16-lane group (xor offsets < 16 stay in-group)
    p += __shfl_xor_sync(0xffffffffu, p, 1);
    p += __shfl_xor_sync(0xffffffffu, p, 2);
    p += __shfl_xor_sync(0xffffffffu, p, 4);
    p += __shfl_xor_sync(0xffffffffu, p, 8);

    float gate = 1.0f / (1.0f + __expf(-p));

    if (valid) {
        float* addr = g_agg + (size_t)d * D + sub * 4;
        asm volatile("red.global.add.v4.f32 [%0], {%1,%2,%3,%4};"
                     :: "l"(addr), "f"(xs.x * gate), "f"(xs.y * gate),
                        "f"(xs.z * gate), "f"(xs.w * gate)
                     : "memory");
        if (sub == 0) atomicAdd(g_cnt + d, 1.0f);
    }
}

// ---------------------------------------------------------------------------
// Kernel 4: node phase.
//   combined = [x[n], agg[n]/max(cnt,1)]  (128)
//   out[n]   = leaky_relu(W_lin @ combined + b, 0.01)
// Block = 256 threads = 8 warps; each warp computes 4 nodes; lane k and k+32.
// ---------------------------------------------------------------------------
__global__ void node_kernel(const float* __restrict__ x,
                            const float* __restrict__ Wl,   // [64,128]
                            const float* __restrict__ b,    // [64]
                            float* __restrict__ out,
                            int N) {
    __shared__ float Wt[2 * D * D];       // transposed [128][64] = 32 KB
    __shared__ float csm[8][4 * 2 * D];   // 8 warps x 4 nodes x 128 = 16 KB

    for (int i = threadIdx.x; i < D * 2 * D; i += blockDim.x) {
        int k = i >> 7;          // output row 0..63
        int j = i & 127;         // input col  0..127
        Wt[j * D + k] = __ldg(Wl + i);
    }
    __syncthreads();

    int warp = threadIdx.x >> 5;
    int lane = threadIdx.x & 31;
    int base = (blockIdx.x * 8 + warp) * 4;
    float* c = csm[warp];

    // stage 4 combined vectors
#pragma unroll
    for (int i = 0; i < 4; i++) {
        int n = min(base + i, N - 1);
        float2 xv = *(const float2*)(x + (size_t)n * D + lane * 2);
        float2 av = *(const float2*)(g_agg + (size_t)n * D + lane * 2);
        float inv = 1.0f / fmaxf(g_cnt[n], 1.0f);
        c[i * 128 + lane * 2]          = xv.x;
        c[i * 128 + lane * 2 + 1]      = xv.y;
        c[i * 128 + D + lane * 2]      = av.x * inv;
        c[i * 128 + D + lane * 2 + 1]  = av.y * inv;
    }
    __syncwarp();

    float b0 = __ldg(b + lane), b1 = __ldg(b + lane + 32);
    float a00 = b0, a01 = b1, a10 = b0, a11 = b1;
    float a20 = b0, a21 = b1, a30 = b0, a31 = b1;

#pragma unroll 4
    for (int jj = 0; jj < 2 * D; jj++) {
        float w0 = Wt[jj * D + lane];        // conflict-free
        float w1 = Wt[jj * D + lane + 32];
        float c0 = c[0 * 128 + jj];          // broadcast
        float c1 = c[1 * 128 + jj];
        float c2 = c[2 * 128 + jj];
        float c3 = c[3 * 128 + jj];
        a00 += c0 * w0; a01 += c0 * w1;
        a10 += c1 * w0; a11 += c1 * w1;
        a20 += c2 * w0; a21 += c2 * w1;
        a30 += c3 * w0; a31 += c3 * w1;
    }

    float acc[4][2] = {{a00, a01}, {a10, a11}, {a20, a21}, {a30, a31}};
#pragma unroll
    for (int i = 0; i < 4; i++) {
        int n = base + i;
        if (n < N) {
            float v0 = acc[i][0], v1 = acc[i][1];
            out[(size_t)n * D + lane]      = v0 > 0.f ? v0 : 0.01f * v0;
            out[(size_t)n * D + lane + 32] = v1 > 0.f ? v1 : 0.01f * v1;
        }
    }
}

// ---------------------------------------------------------------------------
extern "C" void kernel_launch(void* const* d_in, const int* in_sizes, int n_in,
                              void* d_out, int out_size) {
    const float* x    = (const float*)d_in[0];
    const int*   src  = (const int*)d_in[1];
    const int*   dst  = (const int*)d_in[2];
    const int*   rel  = (const int*)d_in[3];
    const float* W_r  = (const float*)d_in[4];
    const float* W_lin= (const float*)d_in[5];
    const float* b_lin= (const float*)d_in[6];
    float* out = (float*)d_out;

    int N = in_sizes[0] / D;     // 50000
    int E = in_sizes[1];         // 800000

    wsum_kernel<<<N_REL, 2 * D>>>(W_r);

    int zthreads = N * (D / 4);  // dominant range (agg float4 count)
    zero_kernel<<<(zthreads + 255) / 256, 256>>>(N);

    int warps = (E + 1) / 2;
    int ethreads = warps * 32;
    edge_kernel<<<(ethreads + 255) / 256, 256>>>(x, src, dst, rel, E);

    node_kernel<<<(N + 31) / 32, 256>>>(x, W_lin, b_lin, out, N);
}

// round 2
// speedup vs baseline: 1.3042x; 1.3042x over previous
#include <cuda_runtime.h>
#include <math.h>

#define N_NODES_MAX 50000
#define D 64
#define N_REL 8

__device__ float g_agg[(size_t)N_NODES_MAX * D];   // 12.8 MB
__device__ float g_cnt[N_NODES_MAX];
__device__ float g_w[N_REL * 2 * D];               // w = W_r.sum(-1) : [8,128]

// ---------------------------------------------------------------------------
// Kernel 1: w[r][j] = sum_k W_r[r][j][k]
// ---------------------------------------------------------------------------
__global__ void wsum_kernel(const float* __restrict__ W_r) {
    int r = blockIdx.x;
    int j = threadIdx.x;
    const float4* row = (const float4*)(W_r + ((size_t)r * 2 * D + j) * D);
    float4 s = make_float4(0.f, 0.f, 0.f, 0.f);
#pragma unroll
    for (int k = 0; k < D / 4; k++) {
        float4 v = __ldg(row + k);
        s.x += v.x; s.y += v.y; s.z += v.z; s.w += v.w;
    }
    g_w[r * 2 * D + j] = (s.x + s.y) + (s.z + s.w);
}

// ---------------------------------------------------------------------------
// Kernel 2: zero agg + cnt
// ---------------------------------------------------------------------------
__global__ void zero_kernel(int n_nodes) {
    int idx = blockIdx.x * blockDim.x + threadIdx.x;
    int n_agg4 = n_nodes * (D / 4);
    if (idx < n_agg4) ((float4*)g_agg)[idx] = make_float4(0.f, 0.f, 0.f, 0.f);
    if (idx < n_nodes) g_cnt[idx] = 0.f;
}

// ---------------------------------------------------------------------------
// Kernel 3: edge phase (unchanged — half-warp per edge, red.global.add.v4)
// ---------------------------------------------------------------------------
__global__ void edge_kernel(const float* __restrict__ x,
                            const int* __restrict__ src,
                            const int* __restrict__ dst,
                            const int* __restrict__ rel,
                            int E) {
    __shared__ float4 wsm[N_REL * 32];
    for (int i = threadIdx.x; i < N_REL * 32; i += blockDim.x)
        wsm[i] = ((const float4*)g_w)[i];
    __syncthreads();

    int warp = (blockIdx.x * blockDim.x + threadIdx.x) >> 5;
    int lane = threadIdx.x & 31;
    int half = lane >> 4;
    int sub  = lane & 15;

    int e = warp * 2 + half;
    bool valid = (e < E);
    int ec = valid ? e : (E - 1);

    int s = __ldg(src + ec);
    int d = __ldg(dst + ec);
    int r = __ldg(rel + ec);

    const float4* x4 = (const float4*)x;
    float4 xs = __ldg(x4 + (size_t)s * (D / 4) + sub);
    float4 xd = __ldg(x4 + (size_t)d * (D / 4) + sub);
    float4 wd = wsm[r * 32 + sub];
    float4 ws = wsm[r * 32 + 16 + sub];

    float p = xd.x * wd.x + xd.y * wd.y + xd.z * wd.z + xd.w * wd.w
            + xs.x * ws.x + xs.y * ws.y + xs.z * ws.z + xs.w * ws.w;
    p += __shfl_xor_sync(0xffffffffu, p, 1);
    p += __shfl_xor_sync(0xffffffffu, p, 2);
    p += __shfl_xor_sync(0xffffffffu, p, 4);
    p += __shfl_xor_sync(0xffffffffu, p, 8);

    float gate = 1.0f / (1.0f + __expf(-p));

    if (valid) {
        float* addr = g_agg + (size_t)d * D + sub * 4;
        asm volatile("red.global.add.v4.f32 [%0], {%1,%2,%3,%4};"
                     :: "l"(addr), "f"(xs.x * gate), "f"(xs.y * gate),
                        "f"(xs.z * gate), "f"(xs.w * gate)
                     : "memory");
        if (sub == 0) atomicAdd(g_cnt + d, 1.0f);
    }
}

// ---------------------------------------------------------------------------
// Kernel 4: node GEMM, register-tiled.
//   Block: 256 threads, tile 128 nodes x 64 outputs.
//   Thread: 4 nodes (tx*4..+3) x 8 outputs (ty*8..+7) = 32 accumulators.
//   combined staged k-major in csm[k][node]; weights chunked in wsm[k][o].
//   Inner loop per warp per k: 512B (conflict-free) + 32B (broadcast) smem
//   for 1024 lane-FMAs => ~0.53 B/FMA (was 3 B/FMA).
// ---------------------------------------------------------------------------
#define BN 128   // nodes per block
#define KC 32    // k-chunk

__global__ __launch_bounds__(256) void node_kernel(
        const float* __restrict__ x,
        const float* __restrict__ Wl,   // [64][128]
        const float* __restrict__ b,    // [64]
        float* __restrict__ out,
        int N) {
    __shared__ float csm[KC][BN];       // 16 KB
    __shared__ float wsm[KC][D];        // 8 KB
    __shared__ float inv_s[BN];

    int tid = threadIdx.x;
    int tx = tid & 31;    // node group (lane)
    int ty = tid >> 5;    // output group (warp)
    int base = blockIdx.x * BN;

    if (tid < BN) {
        int n = min(base + tid, N - 1);
        inv_s[tid] = 1.0f / fmaxf(g_cnt[n], 1.0f);
    }

    // accumulators init with bias
    float acc[4][8];
    float bias[8];
#pragma unroll
    for (int j = 0; j < 8; j++) bias[j] = __ldg(b + ty * 8 + j);
#pragma unroll
    for (int i = 0; i < 4; i++)
#pragma unroll
        for (int j = 0; j < 8; j++) acc[i][j] = bias[j];

    __syncthreads();

#pragma unroll
    for (int kc = 0; kc < 4; kc++) {
        // ---- stage combined chunk transposed: csm[k][node] ----
        // chunks 0,1 come from x; chunks 2,3 from agg * inv (64-aligned)
        {
            int row = tid >> 1;                 // 0..127 node within tile
            int c4b = (tid & 1) * 16;           // first/second 16 floats of chunk
            int n = min(base + row, N - 1);
            const float4* srcp;
            int kglob = kc * KC;                // global k of chunk start
            float scale;
            if (kc < 2) {
                srcp = (const float4*)(x + (size_t)n * D + kglob);
                scale = 1.0f;
            } else {
                srcp = (const float4*)(g_agg + (size_t)n * D + (kglob - D));
                scale = inv_s[row];
            }
#pragma unroll
            for (int q = 0; q < 4; q++) {
                float4 v = __ldg(srcp + (c4b >> 2) + q);
                int k0 = c4b + q * 4;
                csm[k0 + 0][row] = v.x * scale;
                csm[k0 + 1][row] = v.y * scale;
                csm[k0 + 2][row] = v.z * scale;
                csm[k0 + 3][row] = v.w * scale;
            }
        }
        // ---- stage weight chunk: wsm[k][o] = Wl[o][kc*32 + k] ----
        {
            // 32*64 = 2048 entries / 256 threads = 8 each
#pragma unroll
            for (int q = 0; q < 8; q++) {
                int idx = tid + q * 256;
                int k = idx >> 6;       // 0..31
                int o = idx & 63;       // 0..63
                wsm[k][o] = __ldg(Wl + (size_t)o * (2 * D) + kc * KC + k);
            }
        }
        __syncthreads();

        // ---- inner product over chunk ----
#pragma unroll
        for (int k = 0; k < KC; k++) {
            float4 cv = *(const float4*)&csm[k][tx * 4];
            float4 w0 = *(const float4*)&wsm[k][ty * 8];
            float4 w1 = *(const float4*)&wsm[k][ty * 8 + 4];
            float cvv[4] = {cv.x, cv.y, cv.z, cv.w};
            float wv[8] = {w0.x, w0.y, w0.z, w0.w, w1.x, w1.y, w1.z, w1.w};
#pragma unroll
            for (int i = 0; i < 4; i++)
#pragma unroll
                for (int j = 0; j < 8; j++)
                    acc[i][j] += cvv[i] * wv[j];
        }
        __syncthreads();
    }

    // ---- epilogue: leaky relu + store ----
#pragma unroll
    for (int i = 0; i < 4; i++) {
        int n = base + tx * 4 + i;
        if (n < N) {
            float* op = out + (size_t)n * D + ty * 8;
            float4 r0, r1;
            r0.x = acc[i][0] > 0.f ? acc[i][0] : 0.01f * acc[i][0];
            r0.y = acc[i][1] > 0.f ? acc[i][1] : 0.01f * acc[i][1];
            r0.z = acc[i][2] > 0.f ? acc[i][2] : 0.01f * acc[i][2];
            r0.w = acc[i][3] > 0.f ? acc[i][3] : 0.01f * acc[i][3];
            r1.x = acc[i][4] > 0.f ? acc[i][4] : 0.01f * acc[i][4];
            r1.y = acc[i][5] > 0.f ? acc[i][5] : 0.01f * acc[i][5];
            r1.z = acc[i][6] > 0.f ? acc[i][6] : 0.01f * acc[i][6];
            r1.w = acc[i][7] > 0.f ? acc[i][7] : 0.01f * acc[i][7];
            *(float4*)op = r0;
            *(float4*)(op + 4) = r1;
        }
    }
}

// ---------------------------------------------------------------------------
extern "C" void kernel_launch(void* const* d_in, const int* in_sizes, int n_in,
                              void* d_out, int out_size) {
    const float* x    = (const float*)d_in[0];
    const int*   src  = (const int*)d_in[1];
    const int*   dst  = (const int*)d_in[2];
    const int*   rel  = (const int*)d_in[3];
    const float* W_r  = (const float*)d_in[4];
    const float* W_lin= (const float*)d_in[5];
    const float* b_lin= (const float*)d_in[6];
    float* out = (float*)d_out;

    int N = in_sizes[0] / D;     // 50000
    int E = in_sizes[1];         // 800000

    wsum_kernel<<<N_REL, 2 * D>>>(W_r);

    int zthreads = N * (D / 4);
    zero_kernel<<<(zthreads + 255) / 256, 256>>>(N);

    int warps = (E + 1) / 2;
    int ethreads = warps * 32;
    edge_kernel<<<(ethreads + 255) / 256, 256>>>(x, src, dst, rel, E);

    node_kernel<<<(N + BN - 1) / BN, 256>>>(x, W_lin, b_lin, out, N);
}